// round 17
// baseline (speedup 1.0000x reference)
#include <cuda_runtime.h>
#include <cuda_fp16.h>
#include <mma.h>
#include <math_constants.h>

using namespace nvcuda;

#define N_NODES 100000
#define MAX_ETOT 3300000   // 3.2M edges + 100k self-loops
#define SCAN_B 1024
#define NSCAN ((N_NODES + SCAN_B - 1) / SCAN_B)   // 98

// ---------------- scratch (device globals; no allocation allowed) ----------
__device__ int      g_is64;
__device__ int      g_cnt[N_NODES];
__device__ int      g_row[N_NODES + 1];
__device__ int      g_woff[N_NODES];
__device__ int      g_bsum[NSCAN];
__device__ int      g_ssrc[MAX_ETOT];
__device__ __align__(16) __half2 g_e1h[MAX_ETOT * 4];  // per-edge 8 heads exp(e), half
__device__ __align__(16) __half2 g_h1h[N_NODES * 32];  // h1 as half2 (64 cols)
__device__ __align__(16) float   g_es1[N_NODES * 8];
__device__ __align__(16) float   g_ed1[N_NODES * 8];
__device__ __align__(16) float   g_d1 [N_NODES * 8];   // 1/denom per (dst, head)
__device__ __align__(16) float   g_x2 [N_NODES * 64];  // ELU'd layer-1 out
__device__ __align__(16) __half  g_h2h[N_NODES * 32];  // h2 as half
__device__ float    g_a2 [MAX_ETOT];                   // layer-2 exp per edge
__device__ float    g_es2[N_NODES];
__device__ float    g_ed2[N_NODES];
__device__ float    g_d2 [N_NODES];
__device__ float    g_out2[N_NODES * 32];
__device__ double   g_pool[32];

// ---------------- helpers ----------------
__device__ __forceinline__ float lrelu(float v) { return v > 0.f ? v : 0.2f * v; }
__device__ __forceinline__ int clampN(int v) {
    return v < 0 ? 0 : (v >= N_NODES ? N_NODES - 1 : v);
}
// fast exp on FMA/ALU pipes (no MUFU). rel err ~2.4e-6 over |x| < 88.
__device__ __forceinline__ float fexp(float x) {
    x = fmaxf(fminf(x, 80.f), -80.f);
    float y = x * 1.4426950408889634f;     // log2(e)
    float fl = rintf(y);
    float f = y - fl;                      // f in [-0.5, 0.5]
    int   i = (int)fl;
    float p =            1.3333558146428443e-3f;
    p = fmaf(p, f, 9.618129107628477e-3f);
    p = fmaf(p, f, 5.550410866482158e-2f);
    p = fmaf(p, f, 2.402265069591007e-1f);
    p = fmaf(p, f, 6.931471805599453e-1f);
    p = fmaf(p, f, 1.0f);
    return __int_as_float((i + 127) << 23) * p;
}
// fetch (src,dst) for logical edge i (self-loops appended past E)
__device__ __forceinline__ void edge_at(const void* eraw, int E, int i,
                                        int& s, int& d) {
    if (i >= E) { s = i - E; d = s; return; }
    if (g_is64) {
        const long long* e64 = (const long long*)eraw;
        s = clampN((int)e64[i]);
        d = clampN((int)e64[E + i]);
    } else {
        const int* e32 = (const int*)eraw;
        s = clampN(e32[i]);
        d = clampN(e32[E + i]);
    }
}

// ---------------- dtype sniff ----------------
__global__ void k_detect(const int* __restrict__ e) {
    __shared__ int any;
    if (threadIdx.x == 0) any = 0;
    __syncthreads();
    int acc = 0;
    for (int i = 2 * threadIdx.x + 1; i < 4096; i += 2 * blockDim.x) acc |= e[i];
    if (acc) atomicOr(&any, 1);
    __syncthreads();
    if (threadIdx.x == 0) g_is64 = (any == 0) ? 1 : 0;
}

// ---------------- init ----------------
__global__ void __launch_bounds__(256) k_init() {
    int j = blockIdx.x * blockDim.x + threadIdx.x;
    if (j < N_NODES) g_cnt[j] = 0;
    if (j < 32)      g_pool[j] = 0.0;
}

// -------- histogram straight from input (no staging arrays) ---------------
__global__ void __launch_bounds__(256) k_hist(const void* __restrict__ eraw,
                                              int E, int Etot) {
    int i = blockIdx.x * blockDim.x + threadIdx.x;
    if (i >= Etot) return;
    int d;
    if (i >= E) d = i - E;
    else if (g_is64) d = clampN((int)((const long long*)eraw)[E + i]);
    else             d = clampN(((const int*)eraw)[E + i]);
    atomicAdd(&g_cnt[d], 1);
}

// ---------------- CSR build ----------------
__global__ void __launch_bounds__(SCAN_B) k_scan1() {
    __shared__ int sh[SCAN_B];
    int t = threadIdx.x;
    int i = blockIdx.x * SCAN_B + t;
    int v = (i < N_NODES) ? g_cnt[i] : 0;
    sh[t] = v;
    __syncthreads();
    for (int o = 1; o < SCAN_B; o <<= 1) {
        int x = (t >= o) ? sh[t - o] : 0;
        __syncthreads();
        sh[t] += x;
        __syncthreads();
    }
    if (i < N_NODES) g_row[i] = sh[t] - v;
    if (t == SCAN_B - 1) g_bsum[blockIdx.x] = sh[t];
}

__global__ void __launch_bounds__(128) k_scan2() {
    __shared__ int sh[128];
    int t = threadIdx.x;
    int v = (t < NSCAN) ? g_bsum[t] : 0;
    sh[t] = v;
    __syncthreads();
    for (int o = 1; o < 128; o <<= 1) {
        int x = (t >= o) ? sh[t - o] : 0;
        __syncthreads();
        sh[t] += x;
        __syncthreads();
    }
    if (t < NSCAN) g_bsum[t] = sh[t] - v;
}

__global__ void __launch_bounds__(256) k_scan3(int Etot) {
    int i = blockIdx.x * blockDim.x + threadIdx.x;
    if (i < N_NODES) {
        int r = g_row[i] + g_bsum[i / SCAN_B];
        g_row[i] = r;
        g_woff[i] = r;
    }
    if (i == 0) g_row[N_NODES] = Etot;
}

__global__ void __launch_bounds__(256) k_scatter(const void* __restrict__ eraw,
                                                 int E, int Etot) {
    int i = blockIdx.x * blockDim.x + threadIdx.x;
    if (i >= Etot) return;
    int s, d;
    edge_at(eraw, E, i, s, d);
    int pos = atomicAdd(&g_woff[d], 1);
    g_ssrc[pos] = s;
}

// ------- GEMM1 (tensor cores, fp16 in / fp32 acc) + fused e1 --------------
// 128 nodes/block, 256 threads = 8 warps; warp w owns rows 16w..16w+15.
__global__ void __launch_bounds__(256) k_gemm1(const float* __restrict__ x,
                                               const float* __restrict__ W,
                                               const float* __restrict__ as,
                                               const float* __restrict__ ad) {
    __shared__ __align__(32) char smem_raw[49152];
    half*  sA = (half*)smem_raw;               // 128 x 128 half (32 KB)
    half*  sB = (half*)(smem_raw + 32768);     // 128 x 64 half (16 KB)
    float* sC = (float*)smem_raw;              // overlay: 128 x 64 fp32 (32 KB)

    int t = threadIdx.x;
    int warp = t >> 5;
    int n0 = blockIdx.x * 128;

    // W1 -> half smem (row-major k x n, ld 64)
    for (int p = t; p < 128 * 32; p += 256) {      // 4096 half2
        int k = p >> 5, c = p & 31;
        float2 v = *(const float2*)&W[k * 64 + 2 * c];
        *(__half2*)&sB[k * 64 + 2 * c] = __floats2half2_rn(v.x, v.y);
    }
    // x tile -> half smem (row-major node x k, ld 128), zero-padded
    for (int p = t; p < 8192; p += 256) {          // 128 rows x 64 half2
        int r = p >> 6, c = p & 63;
        int gr = n0 + r;
        float2 v = make_float2(0.f, 0.f);
        if (gr < N_NODES) v = *(const float2*)&x[(size_t)gr * 128 + 2 * c];
        *(__half2*)&sA[r * 128 + 2 * c] = __floats2half2_rn(v.x, v.y);
    }
    __syncthreads();

    wmma::fragment<wmma::accumulator, 16, 16, 16, float> c[4];
#pragma unroll
    for (int j = 0; j < 4; j++) wmma::fill_fragment(c[j], 0.f);
#pragma unroll
    for (int k0 = 0; k0 < 128; k0 += 16) {
        wmma::fragment<wmma::matrix_a, 16, 16, 16, half, wmma::row_major> a;
        wmma::load_matrix_sync(a, sA + warp * 16 * 128 + k0, 128);
#pragma unroll
        for (int j = 0; j < 4; j++) {
            wmma::fragment<wmma::matrix_b, 16, 16, 16, half, wmma::row_major> b;
            wmma::load_matrix_sync(b, sB + k0 * 64 + j * 16, 64);
            wmma::mma_sync(c[j], a, b, c[j]);
        }
    }
    __syncthreads();   // all reads of sA done before overlay write
#pragma unroll
    for (int j = 0; j < 4; j++)
        wmma::store_matrix_sync(sC + warp * 16 * 64 + j * 16, c[j], 64,
                                wmma::mem_row_major);
    __syncthreads();

    // epilogue: h1 (half) + es1/ed1; 1024 tasks = 128 rows x 8 heads
    for (int q = t; q < 1024; q += 256) {
        int r = q >> 3, h = q & 7;
        int n = n0 + r;
        if (n >= N_NODES) continue;
        const float* cr = sC + r * 64 + h * 8;
        float es = 0.f, ed = 0.f;
        __half2 hp[4];
#pragma unroll
        for (int j = 0; j < 8; j++) {
            float v = cr[j];
            es += v * as[h * 8 + j];
            ed += v * ad[h * 8 + j];
        }
#pragma unroll
        for (int j = 0; j < 4; j++)
            hp[j] = __floats2half2_rn(cr[2 * j], cr[2 * j + 1]);
        *(uint4*)&g_h1h[(size_t)n * 32 + h * 4] = *(uint4*)hp;
        g_es1[n * 8 + h] = es;
        g_ed1[n * 8 + h] = ed;
    }
}

// ------ layer-1 softmax: single pass, max-free; exps stored as half ------
__global__ void __launch_bounds__(256) k_soft1() {
    int d = (blockIdx.x * blockDim.x + threadIdx.x) >> 5;
    int lane = threadIdx.x & 31;
    if (d >= N_NODES) return;
    int beg = g_row[d], end = g_row[d + 1];
    float4 eda = *(const float4*)&g_ed1[d * 8];
    float4 edb = *(const float4*)&g_ed1[d * 8 + 4];
    float ed[8] = {eda.x, eda.y, eda.z, eda.w, edb.x, edb.y, edb.z, edb.w};
    float sum[8] = {0.f, 0.f, 0.f, 0.f, 0.f, 0.f, 0.f, 0.f};
    for (int e = beg + lane; e < end; e += 32) {
        int s = g_ssrc[e];
        float4 sa = *(const float4*)&g_es1[s * 8];
        float4 sb = *(const float4*)&g_es1[s * 8 + 4];
        float ex[8] = {fexp(lrelu(sa.x + ed[0])), fexp(lrelu(sa.y + ed[1])),
                       fexp(lrelu(sa.z + ed[2])), fexp(lrelu(sa.w + ed[3])),
                       fexp(lrelu(sb.x + ed[4])), fexp(lrelu(sb.y + ed[5])),
                       fexp(lrelu(sb.z + ed[6])), fexp(lrelu(sb.w + ed[7]))};
        __half2 hp[4];
#pragma unroll
        for (int j = 0; j < 4; j++) hp[j] = __floats2half2_rn(ex[2 * j], ex[2 * j + 1]);
        *(uint4*)&g_e1h[(size_t)e * 4] = *(uint4*)hp;
#pragma unroll
        for (int h = 0; h < 8; h++) sum[h] += ex[h];
    }
#pragma unroll
    for (int h = 0; h < 8; h++)
#pragma unroll
        for (int o = 16; o > 0; o >>= 1)
            sum[h] += __shfl_xor_sync(0xffffffffu, sum[h], o);
    if (lane == 0) {
        *(float4*)&g_d1[d * 8] =
            make_float4(1.f / sum[0], 1.f / sum[1], 1.f / sum[2], 1.f / sum[3]);
        *(float4*)&g_d1[d * 8 + 4] =
            make_float4(1.f / sum[4], 1.f / sum[5], 1.f / sum[6], 1.f / sum[7]);
    }
}

// ---- layer-1 aggregation + fused ELU(+b1): lane owns features 2l,2l+1 ----
__global__ void __launch_bounds__(256) k_agg1c(const float* __restrict__ b1) {
    int d = (blockIdx.x * blockDim.x + threadIdx.x) >> 5;
    int lane = threadIdx.x & 31;
    if (d >= N_NODES) return;
    int beg = g_row[d], end = g_row[d + 1];
    int h = lane >> 2;                         // head of features 2l, 2l+1
    float rd = g_d1[d * 8 + h];
    float2 bv = *(const float2*)&b1[2 * lane];
    float accx = 0.f, accy = 0.f;
#pragma unroll 4
    for (int e = beg; e < end; e++) {
        int s = g_ssrc[e];
        __half2 ap = g_e1h[(size_t)e * 4 + (h >> 1)];
        float2 af = __half22float2(ap);
        float a = (h & 1) ? af.y : af.x;
        float2 v = __half22float2(g_h1h[(size_t)s * 32 + lane]);
        accx += a * v.x;
        accy += a * v.y;
    }
    float vx = accx * rd + bv.x;
    float vy = accy * rd + bv.y;
    vx = vx > 0.f ? vx : expm1f(vx);
    vy = vy > 0.f ? vy : expm1f(vy);
    *(float2*)&g_x2[(size_t)d * 64 + 2 * lane] = make_float2(vx, vy);
}

// ------ GEMM2 + fused e2: h2(half) = x2 @ W2; es2/ed2 via width-8 shfl ----
__global__ void __launch_bounds__(256) k_gemm2(const float* __restrict__ W,
                                               const float* __restrict__ as,
                                               const float* __restrict__ ad) {
    __shared__ __align__(16) float sW[64 * 32];
    __shared__ __align__(16) float sx[32 * 64];
    int t = threadIdx.x;
    const float4* W4 = (const float4*)W;
    float4* sW4 = (float4*)sW;
#pragma unroll
    for (int i = 0; i < 2; i++) sW4[t + i * 256] = W4[t + i * 256];
    const float4* x4 = (const float4*)(g_x2 + (size_t)blockIdx.x * 32 * 64);
    float4* sx4 = (float4*)sx;
#pragma unroll
    for (int i = 0; i < 2; i++) sx4[t + i * 256] = x4[t + i * 256];
    __syncthreads();
    int ln = t >> 3, g = t & 7;
    float4 acc = make_float4(0.f, 0.f, 0.f, 0.f);
    const float* xr = sx + ln * 64;
#pragma unroll 8
    for (int k = 0; k < 64; k++) {
        float xv = xr[k];
        float4 w = *(const float4*)&sW[k * 32 + g * 4];
        acc.x += xv * w.x; acc.y += xv * w.y; acc.z += xv * w.z; acc.w += xv * w.w;
    }
    int node = blockIdx.x * 32 + ln;
    __half2 hp0 = __floats2half2_rn(acc.x, acc.y);
    __half2 hp1 = __floats2half2_rn(acc.z, acc.w);
    __half2* h2p = (__half2*)g_h2h;
    h2p[(size_t)node * 16 + g * 2]     = hp0;
    h2p[(size_t)node * 16 + g * 2 + 1] = hp1;
    float4 av = *(const float4*)&as[g * 4];
    float4 bvv = *(const float4*)&ad[g * 4];
    float es = acc.x * av.x + acc.y * av.y + acc.z * av.z + acc.w * av.w;
    float edv = acc.x * bvv.x + acc.y * bvv.y + acc.z * bvv.z + acc.w * bvv.w;
#pragma unroll
    for (int o = 4; o > 0; o >>= 1) {
        es  += __shfl_down_sync(0xffffffffu, es, o, 8);
        edv += __shfl_down_sync(0xffffffffu, edv, o, 8);
    }
    if (g == 0) { g_es2[node] = es; g_ed2[node] = edv; }
}

// ------ layer-2 softmax: single pass, max-free ---------------------------
__global__ void __launch_bounds__(256) k_soft2() {
    int d = (blockIdx.x * blockDim.x + threadIdx.x) >> 5;
    int lane = threadIdx.x & 31;
    if (d >= N_NODES) return;
    int beg = g_row[d], end = g_row[d + 1];
    float edd = g_ed2[d];
    float sum = 0.f;
    for (int e = beg + lane; e < end; e += 32) {
        float ex = fexp(lrelu(g_es2[g_ssrc[e]] + edd));
        g_a2[e] = ex;
        sum += ex;
    }
#pragma unroll
    for (int o = 16; o > 0; o >>= 1)
        sum += __shfl_xor_sync(0xffffffffu, sum, o);
    if (lane == 0) g_d2[d] = 1.f / sum;
}

// ---------------- layer-2 aggregation: warp per dst, half h2 --------------
__global__ void __launch_bounds__(256) k_agg2c() {
    int d = (blockIdx.x * blockDim.x + threadIdx.x) >> 5;
    int lane = threadIdx.x & 31;
    if (d >= N_NODES) return;
    int beg = g_row[d], end = g_row[d + 1];
    float rd = g_d2[d];
    float acc = 0.f;
#pragma unroll 4
    for (int e = beg; e < end; e++) {
        int s = g_ssrc[e];
        float a = g_a2[e];
        acc += a * __half2float(g_h2h[(size_t)s * 32 + lane]);
    }
    g_out2[(size_t)d * 32 + lane] = acc * rd;
}

// ---------------- pooling (double accumulation) ----------------
__global__ void __launch_bounds__(256) k_pool() {
    __shared__ float sred[256];
    int c = threadIdx.x & 31;
    int grp = threadIdx.x >> 5;
    float acc = 0.f;
    for (int row = blockIdx.x * 8 + grp; row < N_NODES; row += gridDim.x * 8)
        acc += g_out2[(size_t)row * 32 + c];
    sred[threadIdx.x] = acc;
    __syncthreads();
    if (threadIdx.x < 32) {
        float s2 = 0.f;
#pragma unroll
        for (int g = 0; g < 8; g++) s2 += sred[g * 32 + threadIdx.x];
        atomicAdd(&g_pool[threadIdx.x], (double)s2);
    }
}

__global__ void k_final(const float* __restrict__ Wr, const float* __restrict__ br,
                        const float* __restrict__ b2, float* __restrict__ out) {
    if (threadIdx.x == 0) {
        double s = 0.0;
#pragma unroll
        for (int c = 0; c < 32; c++)
            s += (g_pool[c] + (double)N_NODES * (double)b2[c]) * (double)Wr[c];
        out[0] = (float)(s + (double)br[0]);
    }
}

// ---------------- launch ----------------
extern "C" void kernel_launch(void* const* d_in, const int* in_sizes, int n_in,
                              void* d_out, int out_size) {
    const float* x   = (const float*)d_in[0];
    const void*  ei  = d_in[1];
    const float* W1  = (const float*)d_in[2];
    const float* as1 = (const float*)d_in[3];
    const float* ad1 = (const float*)d_in[4];
    const float* b1  = (const float*)d_in[5];
    const float* W2  = (const float*)d_in[6];
    const float* as2 = (const float*)d_in[7];
    const float* ad2 = (const float*)d_in[8];
    const float* b2  = (const float*)d_in[9];
    const float* Wr  = (const float*)d_in[10];
    const float* br  = (const float*)d_in[11];
    float* out = (float*)d_out;

    int E = in_sizes[1] / 2;           // 3,200,000
    int Etot = E + N_NODES;            // +self loops
    int WPD = (N_NODES + 7) / 8;       // warp-per-dst grid (8 warps/block)

    k_detect<<<1, 256>>>((const int*)ei);
    k_init<<<(N_NODES + 255) / 256, 256>>>();
    k_hist<<<(Etot + 255) / 256, 256>>>(ei, E, Etot);
    k_scan1<<<NSCAN, SCAN_B>>>();
    k_scan2<<<1, 128>>>();
    k_scan3<<<(N_NODES + 255) / 256, 256>>>(Etot);
    k_scatter<<<(Etot + 255) / 256, 256>>>(ei, E, Etot);
    k_gemm1<<<(N_NODES + 127) / 128, 256>>>(x, W1, as1, ad1);
    k_soft1<<<WPD, 256>>>();
    k_agg1c<<<WPD, 256>>>(b1);
    k_gemm2<<<N_NODES / 32, 256>>>(W2, as2, ad2);
    k_soft2<<<WPD, 256>>>();
    k_agg2c<<<WPD, 256>>>();
    k_pool<<<512, 256>>>();
    k_final<<<1, 32>>>(Wr, br, b2, out);
}